// round 3
// baseline (speedup 1.0000x reference)
#include <cuda_runtime.h>
#include <stdint.h>

// Problem constants (fixed by the dataset)
#define NN 100000      // nodes
#define F0 128
#define F1 64
#define F2 40

// Vector RED (red.global.add.v4.f32, sm_90+). Set to 0 to fall back to
// scalar atomicAdd if a toolchain/driver issue with the vector form appears.
#define USE_VEC_RED 1

// ---------------- scratch (static device globals; allocation-free) ----------
__device__ __align__(16) float g_h1  [NN * F1];   // 25.6 MB
__device__ __align__(16) float g_agg1[NN * F1];   // 25.6 MB
__device__ __align__(16) float g_h2  [NN * F2];   // 16 MB
__device__ __align__(16) float g_agg2[NN * F2];   // 16 MB
__device__ int   g_deg[NN];
__device__ float g_invsqrt[NN];
__device__ float g_invdeg[NN];

// ---------------- helpers ---------------------------------------------------
__device__ __forceinline__ void red_add_v4(float* addr, float4 v) {
#if USE_VEC_RED
    asm volatile("red.global.add.v4.f32 [%0], {%1, %2, %3, %4};"
                 :: "l"(addr), "f"(v.x), "f"(v.y), "f"(v.z), "f"(v.w)
                 : "memory");
#else
    atomicAdd(addr + 0, v.x);
    atomicAdd(addr + 1, v.y);
    atomicAdd(addr + 2, v.z);
    atomicAdd(addr + 3, v.w);
#endif
}

// ---------------- kernels ---------------------------------------------------

// Zero agg1, agg2 (as float4) and deg counters. Grid-stride.
__global__ void zero_kernel() {
    const int n1 = NN * (F1 / 4);          // 1.6M float4
    const int n2 = NN * (F2 / 4);          // 1.0M float4
    float4 z = make_float4(0.f, 0.f, 0.f, 0.f);
    for (int i = blockIdx.x * blockDim.x + threadIdx.x; i < n1 + n2;
         i += gridDim.x * blockDim.x) {
        if (i < n1) reinterpret_cast<float4*>(g_agg1)[i] = z;
        else        reinterpret_cast<float4*>(g_agg2)[i - n1] = z;
        if (i < NN) g_deg[i] = 0;
    }
}

// Degree histogram over dst (self-loop added later as +1).
__global__ void deg_kernel(const int* __restrict__ dst, int E) {
    int i = blockIdx.x * blockDim.x + threadIdx.x;
    if (i < E) atomicAdd(&g_deg[dst[i]], 1);
}

__global__ void invsqrt_kernel() {
    int i = blockIdx.x * blockDim.x + threadIdx.x;
    if (i < NN) {
        float d = (float)(g_deg[i] + 1);
        float r = rsqrtf(d);
        g_invsqrt[i] = r;
        g_invdeg[i]  = r * r;   // matches reference's inv_sqrt*inv_sqrt
    }
}

// h1 = x @ W1   (100000x128 @ 128x64), fp32. W1 in SMEM, thread-per-row.
__global__ __launch_bounds__(128) void gemm1_kernel(const float* __restrict__ x,
                                                    const float* __restrict__ W1) {
    __shared__ float sW[F0 * F1];           // 32 KB
    int tid = threadIdx.x;
    for (int i = tid; i < F0 * F1; i += 128) sW[i] = W1[i];
    __syncthreads();

    int row = blockIdx.x * 128 + tid;
    if (row >= NN) return;

    float acc[F1];
    #pragma unroll
    for (int j = 0; j < F1; ++j) acc[j] = 0.f;

    const float4* xr = reinterpret_cast<const float4*>(x + (size_t)row * F0);
    #pragma unroll 2
    for (int k4 = 0; k4 < F0 / 4; ++k4) {
        float4 xv = xr[k4];
        float xa[4] = {xv.x, xv.y, xv.z, xv.w};
        #pragma unroll
        for (int kk = 0; kk < 4; ++kk) {
            float xs = xa[kk];
            const float4* w4 = reinterpret_cast<const float4*>(sW + (k4 * 4 + kk) * F1);
            #pragma unroll
            for (int j = 0; j < F1 / 4; ++j) {
                float4 w = w4[j];
                acc[4*j+0] = fmaf(xs, w.x, acc[4*j+0]);
                acc[4*j+1] = fmaf(xs, w.y, acc[4*j+1]);
                acc[4*j+2] = fmaf(xs, w.z, acc[4*j+2]);
                acc[4*j+3] = fmaf(xs, w.w, acc[4*j+3]);
            }
        }
    }
    float4* out = reinterpret_cast<float4*>(g_h1 + (size_t)row * F1);
    #pragma unroll
    for (int j = 0; j < F1 / 4; ++j)
        out[j] = make_float4(acc[4*j], acc[4*j+1], acc[4*j+2], acc[4*j+3]);
}

// Layer-1 scatter: agg1[dst] += h1[src] * norm.
// 8 threads per edge; each thread handles 2 float4 lanes.
__global__ __launch_bounds__(256) void scatter1_kernel(const int* __restrict__ src,
                                                       const int* __restrict__ dst, int E) {
    int i = blockIdx.x * blockDim.x + threadIdx.x;
    int total = E * 8;
    if (i >= total) return;
    int e = i >> 3;
    int c = (i & 7) * 2;           // float4 lane pair: c, c+1
    int s = __ldg(src + e);
    int d = __ldg(dst + e);
    float nr = __ldg(g_invsqrt + s) * __ldg(g_invsqrt + d);
    const float4* hp = reinterpret_cast<const float4*>(g_h1 + (size_t)s * F1) + c;
    float*        ap = g_agg1 + (size_t)d * F1 + c * 4;
    float4 v0 = hp[0];
    float4 v1 = hp[1];
    v0.x *= nr; v0.y *= nr; v0.z *= nr; v0.w *= nr;
    v1.x *= nr; v1.y *= nr; v1.z *= nr; v1.w *= nr;
    red_add_v4(ap,     v0);
    red_add_v4(ap + 4, v1);
}

// out1 = relu(agg1 + h1 * invdeg);  h2 = out1 @ W2  (64 -> 40). W2 in SMEM.
__global__ __launch_bounds__(128) void fuse2_kernel(const float* __restrict__ W2) {
    __shared__ float sW[F1 * F2];           // 10.25 KB
    int tid = threadIdx.x;
    for (int i = tid; i < F1 * F2; i += 128) sW[i] = W2[i];
    __syncthreads();

    int row = blockIdx.x * 128 + tid;
    if (row >= NN) return;

    float o[F1];
    const float4* ag = reinterpret_cast<const float4*>(g_agg1 + (size_t)row * F1);
    const float4* hr = reinterpret_cast<const float4*>(g_h1   + (size_t)row * F1);
    float id = g_invdeg[row];
    #pragma unroll
    for (int j = 0; j < F1 / 4; ++j) {
        float4 a = ag[j];
        float4 h = hr[j];
        o[4*j+0] = fmaxf(fmaf(h.x, id, a.x), 0.f);
        o[4*j+1] = fmaxf(fmaf(h.y, id, a.y), 0.f);
        o[4*j+2] = fmaxf(fmaf(h.z, id, a.z), 0.f);
        o[4*j+3] = fmaxf(fmaf(h.w, id, a.w), 0.f);
    }

    float acc[F2];
    #pragma unroll
    for (int j = 0; j < F2; ++j) acc[j] = 0.f;

    #pragma unroll 4
    for (int k = 0; k < F1; ++k) {
        float ov = o[k];
        const float4* w4 = reinterpret_cast<const float4*>(sW + k * F2);  // k*160B: 16B aligned
        #pragma unroll
        for (int j = 0; j < F2 / 4; ++j) {
            float4 w = w4[j];
            acc[4*j+0] = fmaf(ov, w.x, acc[4*j+0]);
            acc[4*j+1] = fmaf(ov, w.y, acc[4*j+1]);
            acc[4*j+2] = fmaf(ov, w.z, acc[4*j+2]);
            acc[4*j+3] = fmaf(ov, w.w, acc[4*j+3]);
        }
    }
    float4* out = reinterpret_cast<float4*>(g_h2 + (size_t)row * F2);
    #pragma unroll
    for (int j = 0; j < F2 / 4; ++j)
        out[j] = make_float4(acc[4*j], acc[4*j+1], acc[4*j+2], acc[4*j+3]);
}

// Layer-2 scatter: agg2[dst] += h2[src] * norm.  10 float4 lanes per edge,
// 5 threads per edge, 2 float4 each.
__global__ __launch_bounds__(256) void scatter2_kernel(const int* __restrict__ src,
                                                       const int* __restrict__ dst, int E) {
    int i = blockIdx.x * blockDim.x + threadIdx.x;
    int total = E * 5;
    if (i >= total) return;
    int e = i / 5;
    int c = (i - e * 5) * 2;       // float4 lane pair
    int s = __ldg(src + e);
    int d = __ldg(dst + e);
    float nr = __ldg(g_invsqrt + s) * __ldg(g_invsqrt + d);
    const float4* hp = reinterpret_cast<const float4*>(g_h2 + (size_t)s * F2) + c;
    float*        ap = g_agg2 + (size_t)d * F2 + c * 4;
    float4 v0 = hp[0];
    float4 v1 = hp[1];
    v0.x *= nr; v0.y *= nr; v0.z *= nr; v0.w *= nr;
    v1.x *= nr; v1.y *= nr; v1.z *= nr; v1.w *= nr;
    red_add_v4(ap,     v0);
    red_add_v4(ap + 4, v1);
}

// out = relu(agg2 + h2 * invdeg)
__global__ __launch_bounds__(256) void final_kernel(float* __restrict__ out) {
    int i = blockIdx.x * blockDim.x + threadIdx.x;
    const int total = NN * (F2 / 4);
    if (i >= total) return;
    int node = i / 10;
    float id = g_invdeg[node];
    float4 a = reinterpret_cast<const float4*>(g_agg2)[i];
    float4 h = reinterpret_cast<const float4*>(g_h2)[i];
    float4 r;
    r.x = fmaxf(fmaf(h.x, id, a.x), 0.f);
    r.y = fmaxf(fmaf(h.y, id, a.y), 0.f);
    r.z = fmaxf(fmaf(h.z, id, a.z), 0.f);
    r.w = fmaxf(fmaf(h.w, id, a.w), 0.f);
    reinterpret_cast<float4*>(out)[i] = r;
}

// ---------------- launch ----------------------------------------------------
extern "C" void kernel_launch(void* const* d_in, const int* in_sizes, int n_in,
                              void* d_out, int out_size) {
    const float* x  = (const float*)d_in[0];   // [N,128]
    const int*   ei = (const int*)  d_in[1];   // [2,E]
    const float* W1 = (const float*)d_in[2];   // [128,64]
    const float* W2 = (const float*)d_in[3];   // [64,40]
    float* out = (float*)d_out;

    int E = in_sizes[1] / 2;
    const int* src = ei;
    const int* dst = ei + E;

    // 1. zero scratch (2.6M float4 + deg)
    zero_kernel<<<2048, 256>>>();
    // 2. degree histogram
    deg_kernel<<<(E + 255) / 256, 256>>>(dst, E);
    // 3. inv sqrt / inv deg
    invsqrt_kernel<<<(NN + 255) / 256, 256>>>();
    // 4. h1 = x @ W1
    gemm1_kernel<<<(NN + 127) / 128, 128>>>(x, W1);
    // 5. layer-1 edge scatter (8 threads/edge, 2 x RED.128 each)
    scatter1_kernel<<<(E * 8 + 255) / 256, 256>>>(src, dst, E);
    // 6. relu + self term + GEMM2 -> h2
    fuse2_kernel<<<(NN + 127) / 128, 128>>>(W2);
    // 7. layer-2 edge scatter (5 threads/edge, 2 x RED.128 each)
    scatter2_kernel<<<(E * 5 + 255) / 256, 256>>>(src, dst, E);
    // 8. final relu -> d_out
    final_kernel<<<(NN * (F2/4) + 255) / 256, 256>>>(out);
}